// round 1
// baseline (speedup 1.0000x reference)
#include <cuda_runtime.h>
#include <cstdint>

// ---------------- static device scratch (no runtime allocation) ----------------
#define V_CAP 50016
__device__ float g_ctable[V_CAP];                 // per-vocab centroid value
__device__ __align__(16) float g_aT2[300 * 32];   // aT2[k*32+j] = a_emb[j][k], zero-padded j>=A
__device__ float g_thr[32];                       // 0.2 * ||a_emb[j]||  (inf pad)
__device__ float g_waon[32];                      // a_weight[j] / ||a_emb[j]||

__device__ __forceinline__ unsigned long long packf2(float a, float b) {
    unsigned long long r;
    asm("mov.b64 %0, {%1, %2};" : "=l"(r) : "f"(a), "f"(b));
    return r;
}
__device__ __forceinline__ float2 unpackf2(unsigned long long v) {
    float2 r;
    asm("mov.b64 {%0, %1}, %2;" : "=f"(r.x), "=f"(r.y) : "l"(v));
    return r;
}

// ---------------- init kernels ----------------
__global__ void init_aspects_kernel(const float* __restrict__ a_emb,
                                    const float* __restrict__ a_weight,
                                    int A, int E) {
    int j = threadIdx.x;
    if (j >= 32) return;
    if (j < A) {
        float s = 0.f;
        for (int e = 0; e < E; e++) { float v = a_emb[j * E + e]; s = fmaf(v, v, s); }
        float an = fmaxf(sqrtf(s), 1e-8f);
        g_thr[j]  = 0.2f * an;
        g_waon[j] = a_weight[j] / an;
    } else {
        g_thr[j]  = 3.0e38f;   // never passes threshold
        g_waon[j] = 0.f;
    }
}

__global__ void init_aT2_kernel(const float* __restrict__ a_emb, int A, int E) {
    int k = blockIdx.x;    // 0..E-1
    int j = threadIdx.x;   // 0..31
    g_aT2[k * 32 + j] = (j < A) ? a_emb[j * E + k] : 0.f;
}

// ---------------- kernel 1: per-vocab centroid table ----------------
// C[v] = max_a { sim > 0.2 ? sim * w_a : 0 },  sim = dot/(an*nx)
// Implemented as: cond = dot > (0.2*an)*nx ; val = dot * (w_a/an) ; C = max(val)/nx
__global__ __launch_bounds__(128) void vocab_kernel(const float* __restrict__ w_emb, int V) {
    __shared__ __align__(16) float s_a[300 * 32];
    for (int i = threadIdx.x; i < 300 * 32 / 4; i += 128)
        ((float4*)s_a)[i] = ((const float4*)g_aT2)[i];
    __syncthreads();

    int row = blockIdx.x * 128 + threadIdx.x;
    if (row >= V) return;

    const float4* wr = (const float4*)(w_emb + (size_t)row * 300);  // 1200B rows, 16B aligned
    const unsigned long long* sa64 = (const unsigned long long*)s_a;

    unsigned long long acc[15];
#pragma unroll
    for (int p = 0; p < 15; p++) acc[p] = 0ULL;   // bit pattern 0 == {0.f,0.f}
    unsigned long long accn = 0ULL;

#pragma unroll 1
    for (int c = 0; c < 75; c++) {                // 75 * 4 = 300 = E
        float4 w4 = wr[c];
#pragma unroll
        for (int kk = 0; kk < 4; kk++) {
            float wv = (kk == 0) ? w4.x : (kk == 1) ? w4.y : (kk == 2) ? w4.z : w4.w;
            unsigned long long w2 = packf2(wv, wv);
            asm("fma.rn.f32x2 %0, %1, %1, %0;" : "+l"(accn) : "l"(w2));   // ||x||^2 in both halves
            const unsigned long long* ap = sa64 + (size_t)(c * 4 + kk) * 16;
#pragma unroll
            for (int p = 0; p < 15; p++) {
                asm("fma.rn.f32x2 %0, %1, %2, %0;" : "+l"(acc[p]) : "l"(w2), "l"(ap[p]));
            }
        }
    }

    float2 nf = unpackf2(accn);
    float nx = fmaxf(sqrtf(nf.x), 1e-8f);

    float best = 0.f;
#pragma unroll
    for (int p = 0; p < 15; p++) {
        float2 d = unpackf2(acc[p]);
        int j0 = 2 * p, j1 = 2 * p + 1;
        if (d.x > g_thr[j0] * nx) best = fmaxf(best, d.x * g_waon[j0]);
        if (d.y > g_thr[j1] * nx) best = fmaxf(best, d.y * g_waon[j1]);
    }
    g_ctable[row] = best / nx;   // 0 stays exactly 0
}

// ---------------- kernel 2: per-row softmax + sparse weighted gather ----------------
__global__ __launch_bounds__(256) void row_kernel(const int* __restrict__ tokens,
                                                  const float* __restrict__ w_emb,
                                                  float* __restrict__ enc,
                                                  float* __restrict__ attn,
                                                  float* __restrict__ cscore,
                                                  int L, int E) {
    int b = blockIdx.x;
    int l = threadIdx.x;
    int lane = l & 31, wid = l >> 5;

    __shared__ float red_m[8], red_s[8];
    __shared__ int   red_n[8];
    __shared__ float bc_max, bc_cs, bc_den;
    __shared__ int   s_woff[8], s_n;
    __shared__ int   s_tok[256];
    __shared__ float s_w[256];

    int tok   = tokens[(size_t)b * L + l];
    float c   = g_ctable[tok];
    float score = (c > 0.f) ? c : -1e9f;
    int   cnt = (tok != 0) ? 1 : 0;

    // phase 1: max(score), sum(c), sum(cnt)
    float m = score, sc = c; int cn = cnt;
#pragma unroll
    for (int o = 16; o; o >>= 1) {
        m  = fmaxf(m, __shfl_xor_sync(0xffffffffu, m, o));
        sc += __shfl_xor_sync(0xffffffffu, sc, o);
        cn += __shfl_xor_sync(0xffffffffu, cn, o);
    }
    if (lane == 0) { red_m[wid] = m; red_s[wid] = sc; red_n[wid] = cn; }
    __syncthreads();
    if (l == 0) {
        float M = red_m[0], S = red_s[0]; int N = red_n[0];
#pragma unroll
        for (int i = 1; i < 8; i++) { M = fmaxf(M, red_m[i]); S += red_s[i]; N += red_n[i]; }
        bc_max = M;
        bc_cs  = S / ((float)N + 1e-5f);
    }
    __syncthreads();

    float M  = bc_max;
    float cs = bc_cs;
    float e  = expf(score - M);   // exactly 0 for inactive positions when M > -1e9; 1 when all -1e9

    // phase 2: sum of exps
    float se = e;
#pragma unroll
    for (int o = 16; o; o >>= 1) se += __shfl_xor_sync(0xffffffffu, se, o);
    if (lane == 0) red_s[wid] = se;
    __syncthreads();
    if (l == 0) {
        float D = red_s[0];
#pragma unroll
        for (int i = 1; i < 8; i++) D += red_s[i];
        bc_den = D;
    }
    __syncthreads();

    float a = e / bc_den;
    attn[(size_t)b * L + l] = a;
    if (l == 0) cscore[b] = cs;

    bool gate = cs > 1e-4f;      // block-uniform
    if (gate) {
        // deterministic compaction of active positions (order = position order)
        bool act = (e > 0.f);
        unsigned mask = __ballot_sync(0xffffffffu, act);
        if (lane == 0) s_woff[wid] = __popc(mask);
        __syncthreads();
        if (l == 0) {
            int o = 0;
#pragma unroll
            for (int i = 0; i < 8; i++) { int t = s_woff[i]; s_woff[i] = o; o += t; }
            s_n = o;
        }
        __syncthreads();
        if (act) {
            int pos = s_woff[wid] + __popc(mask & ((1u << lane) - 1u));
            s_tok[pos] = tok;
            s_w[pos]   = a;
        }
        __syncthreads();
        int n = s_n;
        for (int j = l; j < E; j += 256) {
            float z = 0.f;
            for (int i = 0; i < n; i++)
                z = fmaf(s_w[i], w_emb[(size_t)s_tok[i] * E + j], z);
            enc[(size_t)b * E + j] = z;
        }
    } else {
        for (int j = l; j < E; j += 256)
            enc[(size_t)b * E + j] = 0.f;
    }
}

// ---------------- launch ----------------
extern "C" void kernel_launch(void* const* d_in, const int* in_sizes, int n_in,
                              void* d_out, int out_size) {
    const int*   inputs = (const int*)d_in[0];     // [B, L] int32
    const float* w_emb  = (const float*)d_in[1];   // [V, E]
    const float* a_emb  = (const float*)d_in[2];   // [A, E]
    const float* a_w    = (const float*)d_in[3];   // [A]

    int BL = in_sizes[0];
    int A  = in_sizes[3];
    int E  = in_sizes[2] / A;        // 300
    int V  = in_sizes[1] / E;        // 50000
    int L  = 256;
    int B  = BL / L;                 // 1024

    init_aspects_kernel<<<1, 32>>>(a_emb, a_w, A, E);
    init_aT2_kernel<<<E, 32>>>(a_emb, A, E);
    vocab_kernel<<<(V + 127) / 128, 128>>>(w_emb, V);

    float* out    = (float*)d_out;
    float* enc    = out;                                   // [B, E]
    float* attn   = out + (size_t)B * E;                   // [B, L]
    float* cscore = out + (size_t)B * E + (size_t)B * L;   // [B]
    row_kernel<<<B, 256>>>(inputs, w_emb, enc, attn, cscore, L, E);
}